// round 13
// baseline (speedup 1.0000x reference)
#include <cuda_runtime.h>
#include <cuda_fp16.h>
#include <math.h>
#include <stdint.h>

// ---------------------------------------------------------------------------
// GPT block: B=4, T=2048, C=1024, H=16, D=64
// ---------------------------------------------------------------------------
#define B_  4
#define T_  2048
#define C_  1024
#define C3_ (3 * C_)
#define H_  16
#define D_  64
#define M_  (B_ * T_)      // 8192
#define FC_ (4 * C_)       // 4096

// ---------------------------------------------------------------------------
// Helpers
// ---------------------------------------------------------------------------
__device__ __forceinline__ uint32_t smem_u32(const void* p) {
    uint32_t a;
    asm("{ .reg .u64 t; cvta.to.shared.u64 t, %1; cvt.u32.u64 %0, t; }"
        : "=r"(a) : "l"(p));
    return a;
}

__device__ __forceinline__ uint32_t pack_hi2(float a, float b) {
    __half2 t = __floats2half2_rn(a, b);
    return *(uint32_t*)&t;
}

__device__ __forceinline__ float gelu_f(float x)
{
    float x3 = x * x * x;
    return 0.5f * x * (1.0f + tanhf(0.7978845608028654f * (x + 0.044715f * x3)));
}

__device__ __forceinline__ void cpa16(uint32_t s, const void* g) {
    asm volatile("cp.async.ca.shared.global [%0], [%1], 16;" :: "r"(s), "l"(g));
}
#define CPA_COMMIT() asm volatile("cp.async.commit_group;" ::: "memory")
#define CPA_WAIT1()  asm volatile("cp.async.wait_group 1;" ::: "memory")
#define CPA_WAIT0()  asm volatile("cp.async.wait_group 0;" ::: "memory")

__device__ __forceinline__ void ldm4(uint32_t* r, uint32_t addr) {
    asm volatile("ldmatrix.sync.aligned.m8n8.x4.shared.b16 {%0,%1,%2,%3}, [%4];"
        : "=r"(r[0]), "=r"(r[1]), "=r"(r[2]), "=r"(r[3]) : "r"(addr));
}

// mma m16n8k16 row.col f32.f16.f16.f32
__device__ __forceinline__ void mma16816(float* d, const uint32_t* a, const uint32_t* b) {
    asm volatile("mma.sync.aligned.m16n8k16.row.col.f32.f16.f16.f32 "
        "{%0,%1,%2,%3}, {%4,%5,%6,%7}, {%8,%9}, {%0,%1,%2,%3};"
        : "+f"(d[0]), "+f"(d[1]), "+f"(d[2]), "+f"(d[3])
        : "r"(a[0]), "r"(a[1]), "r"(a[2]), "r"(a[3]), "r"(b[0]), "r"(b[1]));
}

// ---------------------------------------------------------------------------
// Scratch (static __device__) — fp16 activations/weights
// ---------------------------------------------------------------------------
__device__ __align__(128) __half g_ln  [M_ * C_];
__device__ __align__(128) __half g_att [M_ * C_];
__device__ __align__(128) __half g_fc  [M_ * FC_];
__device__ __align__(128) __half g_qkv [M_ * C3_];
__device__ __align__(128) __half g_wqkv[C3_ * C_];
__device__ __align__(128) __half g_wo  [C_ * C_];
__device__ __align__(128) __half g_wf  [FC_ * C_];
__device__ __align__(128) __half g_wp  [C_ * FC_];
__device__ __align__(128) float g_bqkv[C3_];
__device__ __align__(128) float g_x1[M_ * C_];

// ---------------------------------------------------------------------------
// ALL weight transposes + fp16 casts in ONE launch.
// ---------------------------------------------------------------------------
__global__ void wsplit_all(const float* __restrict__ Wq, const float* __restrict__ Wk,
                           const float* __restrict__ Wv, const float* __restrict__ Wo,
                           const float* __restrict__ Wfc, const float* __restrict__ Wpj,
                           __half* __restrict__ qkv, __half* __restrict__ wo,
                           __half* __restrict__ wf,  __half* __restrict__ wp)
{
    const int bid = blockIdx.x;
    const float* W;
    __half* Th;
    int K, N, t;
    if (bid < 3072) {
        int e = bid >> 10;  t = bid & 1023;
        W  = (e == 0) ? Wq : (e == 1) ? Wk : Wv;
        Th = qkv + (size_t)e * C_ * C_;
        K = C_;  N = C_;
    } else if (bid < 4096) {
        t = bid - 3072;  W = Wo;  Th = wo;  K = C_;  N = C_;
    } else if (bid < 8192) {
        t = bid - 4096;  W = Wfc; Th = wf;  K = C_;  N = FC_;
    } else {
        t = bid - 8192;  W = Wpj; Th = wp;  K = FC_; N = C_;
    }
    const int nX = N >> 5;
    const int bx = t % nX, by = t / nX;

    __shared__ float ts[32][33];
    int tx = threadIdx.x & 31, ty = threadIdx.x >> 5;
    #pragma unroll
    for (int i = 0; i < 4; i++) {
        int k = by * 32 + ty + i * 8;
        ts[ty + i * 8][tx] = W[(size_t)k * N + bx * 32 + tx];
    }
    __syncthreads();
    #pragma unroll
    for (int i = 0; i < 4; i++) {
        int n = bx * 32 + ty + i * 8;
        int k = by * 32 + tx;
        Th[(size_t)n * K + k] = __float2half(ts[tx][ty + i * 8]);
    }
}

__global__ void bias3_kernel(const float* __restrict__ a, const float* __restrict__ b,
                             const float* __restrict__ c, float* __restrict__ o)
{
    int i = blockIdx.x * 256 + threadIdx.x;
    if (i < C_) { o[i] = a[i]; o[C_ + i] = b[i]; o[2 * C_ + i] = c[i]; }
}

// ---------------------------------------------------------------------------
// LayerNorm -> fp16
// ---------------------------------------------------------------------------
__global__ void ln_kernel(const float* __restrict__ x,
                          const float* __restrict__ gamma,
                          const float* __restrict__ beta,
                          __half* __restrict__ y)
{
    int row = blockIdx.x;
    int t   = threadIdx.x;
    const float4* xr = (const float4*)(x + (size_t)row * C_);
    float4 xv = xr[t];

    float s  = xv.x + xv.y + xv.z + xv.w;
    float ss = fmaf(xv.x, xv.x, fmaf(xv.y, xv.y, fmaf(xv.z, xv.z, xv.w * xv.w)));
    #pragma unroll
    for (int o = 16; o > 0; o >>= 1) {
        s  += __shfl_xor_sync(0xffffffffu, s,  o);
        ss += __shfl_xor_sync(0xffffffffu, ss, o);
    }
    __shared__ float rs[8], rss[8];
    __shared__ float s_mu, s_inv;
    int w = t >> 5, lane = t & 31;
    if (lane == 0) { rs[w] = s; rss[w] = ss; }
    __syncthreads();
    if (t == 0) {
        float ts = 0.f, tss = 0.f;
        #pragma unroll
        for (int i = 0; i < 8; i++) { ts += rs[i]; tss += rss[i]; }
        float mu  = ts * (1.0f / (float)C_);
        float var = tss * (1.0f / (float)C_) - mu * mu;
        s_mu = mu;  s_inv = rsqrtf(var + 1e-5f);
    }
    __syncthreads();
    float mu = s_mu, inv = s_inv;

    float4 gv = ((const float4*)gamma)[t];
    float4 bv = ((const float4*)beta)[t];
    float o0 = (xv.x - mu) * inv * gv.x + bv.x;
    float o1 = (xv.y - mu) * inv * gv.y + bv.y;
    float o2 = (xv.z - mu) * inv * gv.z + bv.z;
    float o3 = (xv.w - mu) * inv * gv.w + bv.w;

    uint2 u;
    u.x = pack_hi2(o0, o1);
    u.y = pack_hi2(o2, o3);
    ((uint2*)(y + (size_t)row * C_))[t] = u;
}

// ---------------------------------------------------------------------------
// Tensor-core GEMM via mma.sync (pure fp16, fp32 accum)
// CTA tile 64x256, BK=32, 256 threads (8 warps, 2M x 4N, warp 32x64).
// 3-stage cp.async pipeline, 2 CTAs/SM for cross-CTA phase overlap.
// ---------------------------------------------------------------------------
#define A_TILE_B (64 * 80)               // 5120
#define B_TILE_B (256 * 80)              // 20480
#define STAGE_B  (A_TILE_B + B_TILE_B)   // 25600
#define NSTAGE   3
#define GEMM_SMEM (NSTAGE * STAGE_B)     // 76800 (x2 CTA = 153600 < 227KB)
#define oA_ 0
#define oB_ A_TILE_B
#define GTHREADS 256

__device__ __forceinline__ void gemm_load_stage(
    uint32_t sbb, const char* gA, const char* gB,
    size_t rowBytes, size_t kb, int tid)
{
    {   // A: 256 segs (64 rows x 4)
        int r = tid >> 2, c = (tid & 3) * 16;
        cpa16(sbb + oA_ + r * 80 + c, gA + (size_t)r * rowBytes + kb + c);
    }
    #pragma unroll
    for (int i = 0; i < 4; i++) {  // B: 1024 segs
        int s = tid + i * 256;
        int r = s >> 2, c = (s & 3) * 16;
        cpa16(sbb + oB_ + r * 80 + c, gB + (size_t)r * rowBytes + kb + c);
    }
    CPA_COMMIT();
}

__global__ void __launch_bounds__(GTHREADS, 2)
gemm_tc(const __half* __restrict__ A,
        const __half* __restrict__ Bm,
        const float* __restrict__ bias, const float* __restrict__ resid,
        float* __restrict__ Cout, __half* __restrict__ outH,
        int Nn, int Kk, int epi)
{
    extern __shared__ __align__(128) char smem[];
    const uint32_t sb = smem_u32(smem);

    const int tid  = threadIdx.x;
    const int wid  = tid >> 5;
    const int lane = tid & 31;
    const int bx = blockIdx.x;      // N tile (256)
    const int by = blockIdx.y;      // M tile (64)
    const int wm = wid >> 2;        // 0..1  rows wm*32..+31
    const int wn = wid & 3;         // 0..3  cols wn*64..+63

    const char* gA = (const char*)(A  + (size_t)(by * 64) * Kk);
    const char* gB = (const char*)(Bm + (size_t)(bx * 256) * Kk);
    const size_t rowBytes = (size_t)Kk * 2;

    const uint32_t aRowOff = (uint32_t)((wm * 32 + (lane & 15)) * 80 + (lane >> 4) * 16);
    const uint32_t bRowOff = (uint32_t)((wn * 64 + (lane & 7) + ((lane >> 4) << 3)) * 80
                                        + ((lane >> 3) & 1) * 16);

    float acc[2][8][4];
    #pragma unroll
    for (int mt = 0; mt < 2; mt++)
        #pragma unroll
        for (int nt = 0; nt < 8; nt++)
            #pragma unroll
            for (int e = 0; e < 4; e++) acc[mt][nt][e] = 0.f;

    const int nch = Kk >> 5;

    gemm_load_stage(sb,           gA, gB, rowBytes, 0,  tid);
    gemm_load_stage(sb + STAGE_B, gA, gB, rowBytes, 64, tid);

    for (int ch = 0; ch < nch; ch++) {
        if (ch == nch - 1) { CPA_WAIT0(); } else { CPA_WAIT1(); }
        __syncthreads();
        if (ch + 2 < nch) {
            gemm_load_stage(sb + ((ch + 2) % NSTAGE) * STAGE_B,
                            gA, gB, rowBytes, (size_t)(ch + 2) * 64, tid);
        }

        const uint32_t buf = sb + (ch % NSTAGE) * STAGE_B;
        const uint32_t aP = buf + oA_ + aRowOff;
        const uint32_t bP = buf + oB_ + bRowOff;

        #pragma unroll
        for (int k16 = 0; k16 < 2; k16++) {
            const uint32_t ko = (uint32_t)(k16 * 32);
            uint32_t af[2][4];
            #pragma unroll
            for (int mt = 0; mt < 2; mt++)
                ldm4(af[mt], aP + (uint32_t)(mt * 16 * 80) + ko);
            #pragma unroll
            for (int p = 0; p < 4; p++) {
                uint32_t rh[4];
                ldm4(rh, bP + (uint32_t)(p * 16 * 80) + ko);
                const int nt0 = 2 * p, nt1 = 2 * p + 1;
                #pragma unroll
                for (int mt = 0; mt < 2; mt++) {
                    mma16816(acc[mt][nt0], af[mt], rh);
                    mma16816(acc[mt][nt1], af[mt], rh + 2);
                }
            }
        }
    }

    // epilogue
    const int rowBase = by * 64 + wm * 32 + (lane >> 2);
    const int colBase = bx * 256 + wn * 64 + (lane & 3) * 2;
    #pragma unroll
    for (int mt = 0; mt < 2; mt++) {
        #pragma unroll
        for (int nt = 0; nt < 8; nt++) {
            const int col = colBase + nt * 8;
            const float b0 = bias[col], b1 = bias[col + 1];
            const int ra = rowBase + mt * 16;
            const int rb = ra + 8;
            float v00 = acc[mt][nt][0] + b0, v01 = acc[mt][nt][1] + b1;
            float v10 = acc[mt][nt][2] + b0, v11 = acc[mt][nt][3] + b1;
            if (epi == 1 || epi == 3) {
                if (epi == 1) {
                    v00 = gelu_f(v00); v01 = gelu_f(v01);
                    v10 = gelu_f(v10); v11 = gelu_f(v11);
                }
                *(uint32_t*)&outH[(size_t)ra * Nn + col] = pack_hi2(v00, v01);
                *(uint32_t*)&outH[(size_t)rb * Nn + col] = pack_hi2(v10, v11);
            } else {
                if (epi == 2) {
                    const float2 r0v = *(const float2*)&resid[(size_t)ra * Nn + col];
                    const float2 r1v = *(const float2*)&resid[(size_t)rb * Nn + col];
                    v00 += r0v.x; v01 += r0v.y; v10 += r1v.x; v11 += r1v.y;
                }
                *(float2*)&Cout[(size_t)ra * Nn + col] = make_float2(v00, v01);
                *(float2*)&Cout[(size_t)rb * Nn + col] = make_float2(v10, v11);
            }
        }
    }
}

// ---------------------------------------------------------------------------
// Tensor-core flash attention (pure fp16, causal).
// qt REVERSED: heavy tiles (long K range) scheduled first for load balance.
// ---------------------------------------------------------------------------
#define STR_ 72
#define SQ_BYTES (128 * STR_ * 2)
#define SK_BYTES (64 * STR_ * 2)
#define ATTN_SMEM (SQ_BYTES + 2 * SK_BYTES)   // 36864

__global__ void __launch_bounds__(256, 1)
attn_tc(const __half* __restrict__ Q_, const __half* __restrict__ K_,
        const __half* __restrict__ V_,
        __half* __restrict__ O_, int qkvStride)
{
    extern __shared__ __align__(128) char smem[];
    const uint32_t sQ = smem_u32(smem);
    const uint32_t sK = sQ + SQ_BYTES;
    const uint32_t sV = sK + SK_BYTES;
    __half* mV = (__half*)(smem + SQ_BYTES + SK_BYTES);

    const int qt = (int)gridDim.x - 1 - (int)blockIdx.x;   // heavy first
    const int h = blockIdx.y, b = blockIdx.z;
    const int tid = threadIdx.x, wid = tid >> 5, lane = tid & 31;
    const int wm = wid;

    const size_t rowB = (size_t)qkvStride * 2;
    const size_t qbase = ((size_t)(b * T_ + qt * 128)) * rowB + (size_t)h * 128;

    #pragma unroll
    for (int i = 0; i < 4; i++) {
        int c = tid + i * 256;
        int r = c >> 3, ch = (c & 7) * 16;
        cpa16(sQ + r * 144 + ch, (const char*)Q_ + qbase + (size_t)r * rowB + ch);
    }
    CPA_COMMIT();

    const uint32_t aOff  = (uint32_t)((wm * 16 + (lane & 15)) * 144 + (lane >> 4) * 16);
    const uint32_t bRow  = (uint32_t)((lane & 7) + ((lane >> 4) << 3));
    const uint32_t bByte = (uint32_t)(((lane >> 3) & 1) * 16);

    uint32_t qf[4][4];
    float oacc[8][4];
    #pragma unroll
    for (int nd = 0; nd < 8; nd++)
        #pragma unroll
        for (int e = 0; e < 4; e++) oacc[nd][e] = 0.f;
    float m0 = -1e30f, m1 = -1e30f, l0 = 0.f, l1 = 0.f;

    const int qr0 = qt * 128 + wm * 16 + (lane >> 2);
    const int nkt = 2 * qt + 2;

    for (int kt = 0; kt < nkt; kt++) {
        __syncthreads();
        const size_t kbase = ((size_t)(b * T_ + kt * 64)) * rowB + (size_t)h * 128;
        #pragma unroll
        for (int i = 0; i < 2; i++) {
            int c = tid + i * 256;
            int r = c >> 3, ch = (c & 7) * 16;
            cpa16(sK + r * 144 + ch, (const char*)K_ + kbase + (size_t)r * rowB + ch);
        }
        CPA_COMMIT();

        uint4 vreg[2];
        int vkey[2], vd0[2];
        #pragma unroll
        for (int i = 0; i < 2; i++) {
            int c = tid + i * 256;
            vkey[i] = c & 63;
            vd0[i]  = (c >> 6) * 8;
            vreg[i] = *(const uint4*)((const char*)V_ + kbase + (size_t)vkey[i] * rowB + (c >> 6) * 16);
        }

        CPA_WAIT0();

        #pragma unroll
        for (int i = 0; i < 2; i++) {
            const __half* eh = (const __half*)&vreg[i];
            #pragma unroll
            for (int j = 0; j < 8; j++)
                mV[(vd0[i] + j) * STR_ + vkey[i]] = eh[j];
        }
        __syncthreads();

        if (kt == 0) {
            #pragma unroll
            for (int ks = 0; ks < 4; ks++)
                ldm4(qf[ks], sQ + aOff + ks * 32);
        }

        // S = Q.K^T
        float sa[8][4];
        #pragma unroll
        for (int nt = 0; nt < 8; nt++)
            #pragma unroll
            for (int e = 0; e < 4; e++) sa[nt][e] = 0.f;

        #pragma unroll
        for (int ks = 0; ks < 4; ks++) {
            uint32_t bh[8][2];
            #pragma unroll
            for (int p = 0; p < 4; p++) {
                uint32_t rh[4];
                ldm4(rh, sK + (p * 16 + bRow) * 144 + bByte + ks * 32);
                bh[2 * p][0] = rh[0]; bh[2 * p][1] = rh[1];
                bh[2 * p + 1][0] = rh[2]; bh[2 * p + 1][1] = rh[3];
            }
            #pragma unroll
            for (int nt = 0; nt < 8; nt++) mma16816(sa[nt], qf[ks], bh[nt]);
        }

        // online softmax
        float tm0 = -1e30f, tm1 = -1e30f;
        #pragma unroll
        for (int nt = 0; nt < 8; nt++) {
            #pragma unroll
            for (int j = 0; j < 2; j++) {
                int kcol = kt * 64 + nt * 8 + (lane & 3) * 2 + j;
                float s0 = sa[nt][j] * 0.125f;
                float s1 = sa[nt][2 + j] * 0.125f;
                if (kcol > qr0)     s0 = -1e30f;
                if (kcol > qr0 + 8) s1 = -1e30f;
                sa[nt][j] = s0;  sa[nt][2 + j] = s1;
                tm0 = fmaxf(tm0, s0);  tm1 = fmaxf(tm1, s1);
            }
        }
        tm0 = fmaxf(tm0, __shfl_xor_sync(0xffffffffu, tm0, 1));
        tm0 = fmaxf(tm0, __shfl_xor_sync(0xffffffffu, tm0, 2));
        tm1 = fmaxf(tm1, __shfl_xor_sync(0xffffffffu, tm1, 1));
        tm1 = fmaxf(tm1, __shfl_xor_sync(0xffffffffu, tm1, 2));

        const float nm0 = fmaxf(m0, tm0), nm1 = fmaxf(m1, tm1);
        const float cr0 = __expf(m0 - nm0), cr1 = __expf(m1 - nm1);
        m0 = nm0; m1 = nm1;

        float rs0 = 0.f, rs1 = 0.f;
        #pragma unroll
        for (int nt = 0; nt < 8; nt++) {
            #pragma unroll
            for (int j = 0; j < 2; j++) {
                float p0 = __expf(sa[nt][j] - m0);
                float p1 = __expf(sa[nt][2 + j] - m1);
                sa[nt][j] = p0;  sa[nt][2 + j] = p1;
                rs0 += p0;  rs1 += p1;
            }
        }
        rs0 += __shfl_xor_sync(0xffffffffu, rs0, 1);
        rs0 += __shfl_xor_sync(0xffffffffu, rs0, 2);
        rs1 += __shfl_xor_sync(0xffffffffu, rs1, 1);
        rs1 += __shfl_xor_sync(0xffffffffu, rs1, 2);
        l0 = l0 * cr0 + rs0;
        l1 = l1 * cr1 + rs1;

        #pragma unroll
        for (int nd = 0; nd < 8; nd++) {
            oacc[nd][0] *= cr0; oacc[nd][1] *= cr0;
            oacc[nd][2] *= cr1; oacc[nd][3] *= cr1;
        }

        uint32_t pH[4][4];
        #pragma unroll
        for (int ks = 0; ks < 4; ks++) {
            const int t0 = 2 * ks, t1 = 2 * ks + 1;
            pH[ks][0] = pack_hi2(sa[t0][0], sa[t0][1]);
            pH[ks][1] = pack_hi2(sa[t0][2], sa[t0][3]);
            pH[ks][2] = pack_hi2(sa[t1][0], sa[t1][1]);
            pH[ks][3] = pack_hi2(sa[t1][2], sa[t1][3]);
        }

        // O += P.V
        #pragma unroll
        for (int ks = 0; ks < 4; ks++) {
            uint32_t vh[8][2];
            #pragma unroll
            for (int p = 0; p < 4; p++) {
                uint32_t rh[4];
                ldm4(rh, sV + (p * 16 + bRow) * 144 + bByte + ks * 32);
                vh[2 * p][0] = rh[0]; vh[2 * p][1] = rh[1];
                vh[2 * p + 1][0] = rh[2]; vh[2 * p + 1][1] = rh[3];
            }
            #pragma unroll
            for (int nd = 0; nd < 8; nd++) mma16816(oacc[nd], pH[ks], vh[nd]);
        }
    }

    const float il0 = 1.0f / l0, il1 = 1.0f / l1;
    const size_t tok0 = (size_t)(b * T_ + qt * 128 + wm * 16 + (lane >> 2));
    const int colb = h * 64 + (lane & 3) * 2;
    #pragma unroll
    for (int nd = 0; nd < 8; nd++) {
        const int col = colb + nd * 8;
        *(uint32_t*)&O_[tok0 * C_ + col]       = pack_hi2(oacc[nd][0] * il0, oacc[nd][1] * il0);
        *(uint32_t*)&O_[(tok0 + 8) * C_ + col] = pack_hi2(oacc[nd][2] * il1, oacc[nd][3] * il1);
    }
}

// ---------------------------------------------------------------------------
// Launch
// ---------------------------------------------------------------------------
extern "C" void kernel_launch(void* const* d_in, const int* in_sizes, int n_in,
                              void* d_out, int out_size)
{
    const float* x      = (const float*)d_in[0];
    const float* Wq     = (const float*)d_in[1];
    const float* bq     = (const float*)d_in[2];
    const float* Wk     = (const float*)d_in[3];
    const float* bk     = (const float*)d_in[4];
    const float* Wv     = (const float*)d_in[5];
    const float* bv     = (const float*)d_in[6];
    const float* Wo     = (const float*)d_in[7];
    const float* bo     = (const float*)d_in[8];
    const float* ln1_g  = (const float*)d_in[9];
    const float* ln1_b  = (const float*)d_in[10];
    const float* ln2_g  = (const float*)d_in[11];
    const float* ln2_b  = (const float*)d_in[12];
    const float* W_fc   = (const float*)d_in[13];
    const float* b_fc   = (const float*)d_in[14];
    const float* W_proj = (const float*)d_in[15];
    const float* b_proj = (const float*)d_in[16];
    float* out = (float*)d_out;

    __half *ln, *att, *fc, *qkv, *wqkv, *wo, *wf, *wp;
    float *x1, *bqkv;
    cudaGetSymbolAddress((void**)&ln,   g_ln);
    cudaGetSymbolAddress((void**)&att,  g_att);
    cudaGetSymbolAddress((void**)&fc,   g_fc);
    cudaGetSymbolAddress((void**)&qkv,  g_qkv);
    cudaGetSymbolAddress((void**)&wqkv, g_wqkv);
    cudaGetSymbolAddress((void**)&wo,   g_wo);
    cudaGetSymbolAddress((void**)&wf,   g_wf);
    cudaGetSymbolAddress((void**)&wp,   g_wp);
    cudaGetSymbolAddress((void**)&x1,   g_x1);
    cudaGetSymbolAddress((void**)&bqkv, g_bqkv);

    cudaFuncSetAttribute(attn_tc, cudaFuncAttributeMaxDynamicSharedMemorySize, ATTN_SMEM);
    cudaFuncSetAttribute(gemm_tc, cudaFuncAttributeMaxDynamicSharedMemorySize, GEMM_SMEM);

    dim3 gQKV(C3_ / 256, M_ / 64);   // (12, 128)
    dim3 gC  (C_  / 256, M_ / 64);   // (4, 128)
    dim3 gF  (FC_ / 256, M_ / 64);   // (16, 128)

    wsplit_all<<<12288, 256>>>(Wq, Wk, Wv, Wo, W_fc, W_proj, wqkv, wo, wf, wp);
    bias3_kernel<<<C_/256, 256>>>(bq, bk, bv, bqkv);
    ln_kernel<<<M_, 256>>>(x, ln1_g, ln1_b, ln);
    gemm_tc<<<gQKV, GTHREADS, GEMM_SMEM>>>(ln, wqkv, bqkv, nullptr,
                                           nullptr, qkv, C3_, C_, 3);
    attn_tc<<<dim3(T_ / 128, H_, B_), 256, ATTN_SMEM>>>(
        qkv, qkv + C_, qkv + 2 * C_, att, C3_);
    // launch 5: Wo projection (ncu -s 5 -c 1 captures THIS)
    gemm_tc<<<gC, GTHREADS, GEMM_SMEM>>>(att, wo, bo, x, x1, nullptr, C_, C_, 2);
    ln_kernel<<<M_, 256>>>(x1, ln2_g, ln2_b, ln);
    gemm_tc<<<gF, GTHREADS, GEMM_SMEM>>>(ln, wf, b_fc, nullptr,
                                         nullptr, fc, FC_, C_, 1);
    gemm_tc<<<gC, GTHREADS, GEMM_SMEM>>>(fc, wp, b_proj, x1, out,
                                         nullptr, C_, FC_, 2);
}

// round 14
// speedup vs baseline: 1.2445x; 1.2445x over previous
#include <cuda_runtime.h>
#include <cuda_fp16.h>
#include <math.h>
#include <stdint.h>

// ---------------------------------------------------------------------------
// GPT block: B=4, T=2048, C=1024, H=16, D=64
// ---------------------------------------------------------------------------
#define B_  4
#define T_  2048
#define C_  1024
#define C3_ (3 * C_)
#define H_  16
#define D_  64
#define M_  (B_ * T_)      // 8192
#define FC_ (4 * C_)       // 4096

// ---------------------------------------------------------------------------
// Helpers
// ---------------------------------------------------------------------------
__device__ __forceinline__ uint32_t smem_u32(const void* p) {
    uint32_t a;
    asm("{ .reg .u64 t; cvta.to.shared.u64 t, %1; cvt.u32.u64 %0, t; }"
        : "=r"(a) : "l"(p));
    return a;
}

__device__ __forceinline__ uint32_t pack_hi2(float a, float b) {
    __half2 t = __floats2half2_rn(a, b);
    return *(uint32_t*)&t;
}

__device__ __forceinline__ float gelu_f(float x)
{
    float x3 = x * x * x;
    return 0.5f * x * (1.0f + tanhf(0.7978845608028654f * (x + 0.044715f * x3)));
}

__device__ __forceinline__ void cpa16(uint32_t s, const void* g) {
    asm volatile("cp.async.ca.shared.global [%0], [%1], 16;" :: "r"(s), "l"(g));
}
#define CPA_COMMIT() asm volatile("cp.async.commit_group;" ::: "memory")
#define CPA_WAIT1()  asm volatile("cp.async.wait_group 1;" ::: "memory")
#define CPA_WAIT0()  asm volatile("cp.async.wait_group 0;" ::: "memory")

__device__ __forceinline__ void ldm4(uint32_t* r, uint32_t addr) {
    asm volatile("ldmatrix.sync.aligned.m8n8.x4.shared.b16 {%0,%1,%2,%3}, [%4];"
        : "=r"(r[0]), "=r"(r[1]), "=r"(r[2]), "=r"(r[3]) : "r"(addr));
}

// mma m16n8k16 row.col f32.f16.f16.f32
__device__ __forceinline__ void mma16816(float* d, const uint32_t* a, const uint32_t* b) {
    asm volatile("mma.sync.aligned.m16n8k16.row.col.f32.f16.f16.f32 "
        "{%0,%1,%2,%3}, {%4,%5,%6,%7}, {%8,%9}, {%0,%1,%2,%3};"
        : "+f"(d[0]), "+f"(d[1]), "+f"(d[2]), "+f"(d[3])
        : "r"(a[0]), "r"(a[1]), "r"(a[2]), "r"(a[3]), "r"(b[0]), "r"(b[1]));
}

// ---------------------------------------------------------------------------
// Scratch (static __device__) — fp16 activations/weights
// ---------------------------------------------------------------------------
__device__ __align__(128) __half g_ln  [M_ * C_];
__device__ __align__(128) __half g_att [M_ * C_];
__device__ __align__(128) __half g_fc  [M_ * FC_];
__device__ __align__(128) __half g_qkv [M_ * C3_];
__device__ __align__(128) __half g_wqkv[C3_ * C_];
__device__ __align__(128) __half g_wo  [C_ * C_];
__device__ __align__(128) __half g_wf  [FC_ * C_];
__device__ __align__(128) __half g_wp  [C_ * FC_];
__device__ __align__(128) float g_bqkv[C3_];
__device__ __align__(128) float g_x1[M_ * C_];

// ---------------------------------------------------------------------------
// ALL weight transposes + fp16 casts in ONE launch.
// ---------------------------------------------------------------------------
__global__ void wsplit_all(const float* __restrict__ Wq, const float* __restrict__ Wk,
                           const float* __restrict__ Wv, const float* __restrict__ Wo,
                           const float* __restrict__ Wfc, const float* __restrict__ Wpj,
                           __half* __restrict__ qkv, __half* __restrict__ wo,
                           __half* __restrict__ wf,  __half* __restrict__ wp)
{
    const int bid = blockIdx.x;
    const float* W;
    __half* Th;
    int K, N, t;
    if (bid < 3072) {
        int e = bid >> 10;  t = bid & 1023;
        W  = (e == 0) ? Wq : (e == 1) ? Wk : Wv;
        Th = qkv + (size_t)e * C_ * C_;
        K = C_;  N = C_;
    } else if (bid < 4096) {
        t = bid - 3072;  W = Wo;  Th = wo;  K = C_;  N = C_;
    } else if (bid < 8192) {
        t = bid - 4096;  W = Wfc; Th = wf;  K = C_;  N = FC_;
    } else {
        t = bid - 8192;  W = Wpj; Th = wp;  K = FC_; N = C_;
    }
    const int nX = N >> 5;
    const int bx = t % nX, by = t / nX;

    __shared__ float ts[32][33];
    int tx = threadIdx.x & 31, ty = threadIdx.x >> 5;
    #pragma unroll
    for (int i = 0; i < 4; i++) {
        int k = by * 32 + ty + i * 8;
        ts[ty + i * 8][tx] = W[(size_t)k * N + bx * 32 + tx];
    }
    __syncthreads();
    #pragma unroll
    for (int i = 0; i < 4; i++) {
        int n = bx * 32 + ty + i * 8;
        int k = by * 32 + tx;
        Th[(size_t)n * K + k] = __float2half(ts[tx][ty + i * 8]);
    }
}

__global__ void bias3_kernel(const float* __restrict__ a, const float* __restrict__ b,
                             const float* __restrict__ c, float* __restrict__ o)
{
    int i = blockIdx.x * 256 + threadIdx.x;
    if (i < C_) { o[i] = a[i]; o[C_ + i] = b[i]; o[2 * C_ + i] = c[i]; }
}

// ---------------------------------------------------------------------------
// LayerNorm -> fp16
// ---------------------------------------------------------------------------
__global__ void ln_kernel(const float* __restrict__ x,
                          const float* __restrict__ gamma,
                          const float* __restrict__ beta,
                          __half* __restrict__ y)
{
    int row = blockIdx.x;
    int t   = threadIdx.x;
    const float4* xr = (const float4*)(x + (size_t)row * C_);
    float4 xv = xr[t];

    float s  = xv.x + xv.y + xv.z + xv.w;
    float ss = fmaf(xv.x, xv.x, fmaf(xv.y, xv.y, fmaf(xv.z, xv.z, xv.w * xv.w)));
    #pragma unroll
    for (int o = 16; o > 0; o >>= 1) {
        s  += __shfl_xor_sync(0xffffffffu, s,  o);
        ss += __shfl_xor_sync(0xffffffffu, ss, o);
    }
    __shared__ float rs[8], rss[8];
    __shared__ float s_mu, s_inv;
    int w = t >> 5, lane = t & 31;
    if (lane == 0) { rs[w] = s; rss[w] = ss; }
    __syncthreads();
    if (t == 0) {
        float ts = 0.f, tss = 0.f;
        #pragma unroll
        for (int i = 0; i < 8; i++) { ts += rs[i]; tss += rss[i]; }
        float mu  = ts * (1.0f / (float)C_);
        float var = tss * (1.0f / (float)C_) - mu * mu;
        s_mu = mu;  s_inv = rsqrtf(var + 1e-5f);
    }
    __syncthreads();
    float mu = s_mu, inv = s_inv;

    float4 gv = ((const float4*)gamma)[t];
    float4 bv = ((const float4*)beta)[t];
    float o0 = (xv.x - mu) * inv * gv.x + bv.x;
    float o1 = (xv.y - mu) * inv * gv.y + bv.y;
    float o2 = (xv.z - mu) * inv * gv.z + bv.z;
    float o3 = (xv.w - mu) * inv * gv.w + bv.w;

    uint2 u;
    u.x = pack_hi2(o0, o1);
    u.y = pack_hi2(o2, o3);
    ((uint2*)(y + (size_t)row * C_))[t] = u;
}

// ---------------------------------------------------------------------------
// Tensor-core GEMM via mma.sync (pure fp16, fp32 accum)
// CTA tile 128x256, BK=64, 512 threads (16 warps, 4M x 4N, warp 32x64).
// 3-stage cp.async pipeline; one __syncthreads per BK=64 chunk
// (half the sync frequency of BK=32).
// ---------------------------------------------------------------------------
#define ROWB_ 144                         // 128B data + 16B pad
#define A_TILE_B (128 * ROWB_)            // 18432
#define B_TILE_B (256 * ROWB_)            // 36864
#define STAGE_B  (A_TILE_B + B_TILE_B)    // 55296
#define NSTAGE   3
#define GEMM_SMEM (NSTAGE * STAGE_B)      // 165888
#define oA_ 0
#define oB_ A_TILE_B
#define GTHREADS 512

__device__ __forceinline__ void gemm_load_stage(
    uint32_t sbb, const char* gA, const char* gB,
    size_t rowBytes, size_t kb, int tid)
{
    // A: 128 rows x 8 segs of 16B = 1024 segs
    #pragma unroll
    for (int i = 0; i < 2; i++) {
        int s = tid + i * 512;
        int r = s >> 3, c = (s & 7) * 16;
        cpa16(sbb + oA_ + r * ROWB_ + c, gA + (size_t)r * rowBytes + kb + c);
    }
    // B: 256 rows x 8 segs = 2048 segs
    #pragma unroll
    for (int i = 0; i < 4; i++) {
        int s = tid + i * 512;
        int r = s >> 3, c = (s & 7) * 16;
        cpa16(sbb + oB_ + r * ROWB_ + c, gB + (size_t)r * rowBytes + kb + c);
    }
    CPA_COMMIT();
}

__global__ void __launch_bounds__(GTHREADS, 1)
gemm_tc(const __half* __restrict__ A,
        const __half* __restrict__ Bm,
        const float* __restrict__ bias, const float* __restrict__ resid,
        float* __restrict__ Cout, __half* __restrict__ outH,
        int Nn, int Kk, int epi)
{
    extern __shared__ __align__(128) char smem[];
    const uint32_t sb = smem_u32(smem);

    const int tid  = threadIdx.x;
    const int wid  = tid >> 5;
    const int lane = tid & 31;
    const int bx = blockIdx.x;      // N tile (256)
    const int by = blockIdx.y;      // M tile (128)
    const int wm = wid >> 2;        // 0..3
    const int wn = wid & 3;         // 0..3

    const char* gA = (const char*)(A  + (size_t)(by * 128) * Kk);
    const char* gB = (const char*)(Bm + (size_t)(bx * 256) * Kk);
    const size_t rowBytes = (size_t)Kk * 2;

    const uint32_t aRowOff = (uint32_t)((wm * 32 + (lane & 15)) * ROWB_ + (lane >> 4) * 16);
    const uint32_t bRowOff = (uint32_t)((wn * 64 + (lane & 7) + ((lane >> 4) << 3)) * ROWB_
                                        + ((lane >> 3) & 1) * 16);

    float acc[2][8][4];
    #pragma unroll
    for (int mt = 0; mt < 2; mt++)
        #pragma unroll
        for (int nt = 0; nt < 8; nt++)
            #pragma unroll
            for (int e = 0; e < 4; e++) acc[mt][nt][e] = 0.f;

    const int nch = Kk >> 6;   // BK=64

    gemm_load_stage(sb,           gA, gB, rowBytes, 0,   tid);
    gemm_load_stage(sb + STAGE_B, gA, gB, rowBytes, 128, tid);

    for (int ch = 0; ch < nch; ch++) {
        if (ch == nch - 1) { CPA_WAIT0(); } else { CPA_WAIT1(); }
        __syncthreads();
        if (ch + 2 < nch) {
            gemm_load_stage(sb + ((ch + 2) % NSTAGE) * STAGE_B,
                            gA, gB, rowBytes, (size_t)(ch + 2) * 128, tid);
        }

        const uint32_t buf = sb + (ch % NSTAGE) * STAGE_B;
        const uint32_t aP = buf + oA_ + aRowOff;
        const uint32_t bP = buf + oB_ + bRowOff;

        #pragma unroll
        for (int ks = 0; ks < 4; ks++) {
            const uint32_t ko = (uint32_t)(ks * 32);
            uint32_t af[2][4];
            #pragma unroll
            for (int mt = 0; mt < 2; mt++)
                ldm4(af[mt], aP + (uint32_t)(mt * 16 * ROWB_) + ko);
            #pragma unroll
            for (int p = 0; p < 4; p++) {
                uint32_t rh[4];
                ldm4(rh, bP + (uint32_t)(p * 16 * ROWB_) + ko);
                const int nt0 = 2 * p, nt1 = 2 * p + 1;
                #pragma unroll
                for (int mt = 0; mt < 2; mt++) {
                    mma16816(acc[mt][nt0], af[mt], rh);
                    mma16816(acc[mt][nt1], af[mt], rh + 2);
                }
            }
        }
    }

    // epilogue
    const int rowBase = by * 128 + wm * 32 + (lane >> 2);
    const int colBase = bx * 256 + wn * 64 + (lane & 3) * 2;
    #pragma unroll
    for (int mt = 0; mt < 2; mt++) {
        #pragma unroll
        for (int nt = 0; nt < 8; nt++) {
            const int col = colBase + nt * 8;
            const float b0 = bias[col], b1 = bias[col + 1];
            const int ra = rowBase + mt * 16;
            const int rb = ra + 8;
            float v00 = acc[mt][nt][0] + b0, v01 = acc[mt][nt][1] + b1;
            float v10 = acc[mt][nt][2] + b0, v11 = acc[mt][nt][3] + b1;
            if (epi == 1 || epi == 3) {
                if (epi == 1) {
                    v00 = gelu_f(v00); v01 = gelu_f(v01);
                    v10 = gelu_f(v10); v11 = gelu_f(v11);
                }
                *(uint32_t*)&outH[(size_t)ra * Nn + col] = pack_hi2(v00, v01);
                *(uint32_t*)&outH[(size_t)rb * Nn + col] = pack_hi2(v10, v11);
            } else {
                if (epi == 2) {
                    const float2 r0v = *(const float2*)&resid[(size_t)ra * Nn + col];
                    const float2 r1v = *(const float2*)&resid[(size_t)rb * Nn + col];
                    v00 += r0v.x; v01 += r0v.y; v10 += r1v.x; v11 += r1v.y;
                }
                *(float2*)&Cout[(size_t)ra * Nn + col] = make_float2(v00, v01);
                *(float2*)&Cout[(size_t)rb * Nn + col] = make_float2(v10, v11);
            }
        }
    }
}

// ---------------------------------------------------------------------------
// Tensor-core flash attention (pure fp16, causal). 2 CTAs/SM.
// qt reversed: heavy tiles first.
// ---------------------------------------------------------------------------
#define STR_ 72
#define SQ_BYTES (128 * STR_ * 2)
#define SK_BYTES (64 * STR_ * 2)
#define ATTN_SMEM (SQ_BYTES + 2 * SK_BYTES)   // 36864

__global__ void __launch_bounds__(256, 2)
attn_tc(const __half* __restrict__ Q_, const __half* __restrict__ K_,
        const __half* __restrict__ V_,
        __half* __restrict__ O_, int qkvStride)
{
    extern __shared__ __align__(128) char smem[];
    const uint32_t sQ = smem_u32(smem);
    const uint32_t sK = sQ + SQ_BYTES;
    const uint32_t sV = sK + SK_BYTES;
    __half* mV = (__half*)(smem + SQ_BYTES + SK_BYTES);

    const int qt = (int)gridDim.x - 1 - (int)blockIdx.x;   // heavy first
    const int h = blockIdx.y, b = blockIdx.z;
    const int tid = threadIdx.x, wid = tid >> 5, lane = tid & 31;
    const int wm = wid;

    const size_t rowB = (size_t)qkvStride * 2;
    const size_t qbase = ((size_t)(b * T_ + qt * 128)) * rowB + (size_t)h * 128;

    #pragma unroll
    for (int i = 0; i < 4; i++) {
        int c = tid + i * 256;
        int r = c >> 3, ch = (c & 7) * 16;
        cpa16(sQ + r * 144 + ch, (const char*)Q_ + qbase + (size_t)r * rowB + ch);
    }
    CPA_COMMIT();

    const uint32_t aOff  = (uint32_t)((wm * 16 + (lane & 15)) * 144 + (lane >> 4) * 16);
    const uint32_t bRow  = (uint32_t)((lane & 7) + ((lane >> 4) << 3));
    const uint32_t bByte = (uint32_t)(((lane >> 3) & 1) * 16);

    uint32_t qf[4][4];
    float oacc[8][4];
    #pragma unroll
    for (int nd = 0; nd < 8; nd++)
        #pragma unroll
        for (int e = 0; e < 4; e++) oacc[nd][e] = 0.f;
    float m0 = -1e30f, m1 = -1e30f, l0 = 0.f, l1 = 0.f;

    const int qr0 = qt * 128 + wm * 16 + (lane >> 2);
    const int nkt = 2 * qt + 2;

    for (int kt = 0; kt < nkt; kt++) {
        __syncthreads();
        const size_t kbase = ((size_t)(b * T_ + kt * 64)) * rowB + (size_t)h * 128;
        #pragma unroll
        for (int i = 0; i < 2; i++) {
            int c = tid + i * 256;
            int r = c >> 3, ch = (c & 7) * 16;
            cpa16(sK + r * 144 + ch, (const char*)K_ + kbase + (size_t)r * rowB + ch);
        }
        CPA_COMMIT();

        uint4 vreg[2];
        int vkey[2], vd0[2];
        #pragma unroll
        for (int i = 0; i < 2; i++) {
            int c = tid + i * 256;
            vkey[i] = c & 63;
            vd0[i]  = (c >> 6) * 8;
            vreg[i] = *(const uint4*)((const char*)V_ + kbase + (size_t)vkey[i] * rowB + (c >> 6) * 16);
        }

        CPA_WAIT0();

        #pragma unroll
        for (int i = 0; i < 2; i++) {
            const __half* eh = (const __half*)&vreg[i];
            #pragma unroll
            for (int j = 0; j < 8; j++)
                mV[(vd0[i] + j) * STR_ + vkey[i]] = eh[j];
        }
        __syncthreads();

        if (kt == 0) {
            #pragma unroll
            for (int ks = 0; ks < 4; ks++)
                ldm4(qf[ks], sQ + aOff + ks * 32);
        }

        // S = Q.K^T
        float sa[8][4];
        #pragma unroll
        for (int nt = 0; nt < 8; nt++)
            #pragma unroll
            for (int e = 0; e < 4; e++) sa[nt][e] = 0.f;

        #pragma unroll
        for (int ks = 0; ks < 4; ks++) {
            uint32_t bh[8][2];
            #pragma unroll
            for (int p = 0; p < 4; p++) {
                uint32_t rh[4];
                ldm4(rh, sK + (p * 16 + bRow) * 144 + bByte + ks * 32);
                bh[2 * p][0] = rh[0]; bh[2 * p][1] = rh[1];
                bh[2 * p + 1][0] = rh[2]; bh[2 * p + 1][1] = rh[3];
            }
            #pragma unroll
            for (int nt = 0; nt < 8; nt++) mma16816(sa[nt], qf[ks], bh[nt]);
        }

        // online softmax
        float tm0 = -1e30f, tm1 = -1e30f;
        #pragma unroll
        for (int nt = 0; nt < 8; nt++) {
            #pragma unroll
            for (int j = 0; j < 2; j++) {
                int kcol = kt * 64 + nt * 8 + (lane & 3) * 2 + j;
                float s0 = sa[nt][j] * 0.125f;
                float s1 = sa[nt][2 + j] * 0.125f;
                if (kcol > qr0)     s0 = -1e30f;
                if (kcol > qr0 + 8) s1 = -1e30f;
                sa[nt][j] = s0;  sa[nt][2 + j] = s1;
                tm0 = fmaxf(tm0, s0);  tm1 = fmaxf(tm1, s1);
            }
        }
        tm0 = fmaxf(tm0, __shfl_xor_sync(0xffffffffu, tm0, 1));
        tm0 = fmaxf(tm0, __shfl_xor_sync(0xffffffffu, tm0, 2));
        tm1 = fmaxf(tm1, __shfl_xor_sync(0xffffffffu, tm1, 1));
        tm1 = fmaxf(tm1, __shfl_xor_sync(0xffffffffu, tm1, 2));

        const float nm0 = fmaxf(m0, tm0), nm1 = fmaxf(m1, tm1);
        const float cr0 = __expf(m0 - nm0), cr1 = __expf(m1 - nm1);
        m0 = nm0; m1 = nm1;

        float rs0 = 0.f, rs1 = 0.f;
        #pragma unroll
        for (int nt = 0; nt < 8; nt++) {
            #pragma unroll
            for (int j = 0; j < 2; j++) {
                float p0 = __expf(sa[nt][j] - m0);
                float p1 = __expf(sa[nt][2 + j] - m1);
                sa[nt][j] = p0;  sa[nt][2 + j] = p1;
                rs0 += p0;  rs1 += p1;
            }
        }
        rs0 += __shfl_xor_sync(0xffffffffu, rs0, 1);
        rs0 += __shfl_xor_sync(0xffffffffu, rs0, 2);
        rs1 += __shfl_xor_sync(0xffffffffu, rs1, 1);
        rs1 += __shfl_xor_sync(0xffffffffu, rs1, 2);
        l0 = l0 * cr0 + rs0;
        l1 = l1 * cr1 + rs1;

        #pragma unroll
        for (int nd = 0; nd < 8; nd++) {
            oacc[nd][0] *= cr0; oacc[nd][1] *= cr0;
            oacc[nd][2] *= cr1; oacc[nd][3] *= cr1;
        }

        uint32_t pH[4][4];
        #pragma unroll
        for (int ks = 0; ks < 4; ks++) {
            const int t0 = 2 * ks, t1 = 2 * ks + 1;
            pH[ks][0] = pack_hi2(sa[t0][0], sa[t0][1]);
            pH[ks][1] = pack_hi2(sa[t0][2], sa[t0][3]);
            pH[ks][2] = pack_hi2(sa[t1][0], sa[t1][1]);
            pH[ks][3] = pack_hi2(sa[t1][2], sa[t1][3]);
        }

        // O += P.V
        #pragma unroll
        for (int ks = 0; ks < 4; ks++) {
            uint32_t vh[8][2];
            #pragma unroll
            for (int p = 0; p < 4; p++) {
                uint32_t rh[4];
                ldm4(rh, sV + (p * 16 + bRow) * 144 + bByte + ks * 32);
                vh[2 * p][0] = rh[0]; vh[2 * p][1] = rh[1];
                vh[2 * p + 1][0] = rh[2]; vh[2 * p + 1][1] = rh[3];
            }
            #pragma unroll
            for (int nd = 0; nd < 8; nd++) mma16816(oacc[nd], pH[ks], vh[nd]);
        }
    }

    const float il0 = 1.0f / l0, il1 = 1.0f / l1;
    const size_t tok0 = (size_t)(b * T_ + qt * 128 + wm * 16 + (lane >> 2));
    const int colb = h * 64 + (lane & 3) * 2;
    #pragma unroll
    for (int nd = 0; nd < 8; nd++) {
        const int col = colb + nd * 8;
        *(uint32_t*)&O_[tok0 * C_ + col]       = pack_hi2(oacc[nd][0] * il0, oacc[nd][1] * il0);
        *(uint32_t*)&O_[(tok0 + 8) * C_ + col] = pack_hi2(oacc[nd][2] * il1, oacc[nd][3] * il1);
    }
}

// ---------------------------------------------------------------------------
// Launch
// ---------------------------------------------------------------------------
extern "C" void kernel_launch(void* const* d_in, const int* in_sizes, int n_in,
                              void* d_out, int out_size)
{
    const float* x      = (const float*)d_in[0];
    const float* Wq     = (const float*)d_in[1];
    const float* bq     = (const float*)d_in[2];
    const float* Wk     = (const float*)d_in[3];
    const float* bk     = (const float*)d_in[4];
    const float* Wv     = (const float*)d_in[5];
    const float* bv     = (const float*)d_in[6];
    const float* Wo     = (const float*)d_in[7];
    const float* bo     = (const float*)d_in[8];
    const float* ln1_g  = (const float*)d_in[9];
    const float* ln1_b  = (const float*)d_in[10];
    const float* ln2_g  = (const float*)d_in[11];
    const float* ln2_b  = (const float*)d_in[12];
    const float* W_fc   = (const float*)d_in[13];
    const float* b_fc   = (const float*)d_in[14];
    const float* W_proj = (const float*)d_in[15];
    const float* b_proj = (const float*)d_in[16];
    float* out = (float*)d_out;

    __half *ln, *att, *fc, *qkv, *wqkv, *wo, *wf, *wp;
    float *x1, *bqkv;
    cudaGetSymbolAddress((void**)&ln,   g_ln);
    cudaGetSymbolAddress((void**)&att,  g_att);
    cudaGetSymbolAddress((void**)&fc,   g_fc);
    cudaGetSymbolAddress((void**)&qkv,  g_qkv);
    cudaGetSymbolAddress((void**)&wqkv, g_wqkv);
    cudaGetSymbolAddress((void**)&wo,   g_wo);
    cudaGetSymbolAddress((void**)&wf,   g_wf);
    cudaGetSymbolAddress((void**)&wp,   g_wp);
    cudaGetSymbolAddress((void**)&x1,   g_x1);
    cudaGetSymbolAddress((void**)&bqkv, g_bqkv);

    cudaFuncSetAttribute(attn_tc, cudaFuncAttributeMaxDynamicSharedMemorySize, ATTN_SMEM);
    cudaFuncSetAttribute(gemm_tc, cudaFuncAttributeMaxDynamicSharedMemorySize, GEMM_SMEM);

    dim3 gQKV(C3_ / 256, M_ / 128);   // (12, 64)
    dim3 gC  (C_  / 256, M_ / 128);   // (4, 64)
    dim3 gF  (FC_ / 256, M_ / 128);   // (16, 64)

    wsplit_all<<<12288, 256>>>(Wq, Wk, Wv, Wo, W_fc, W_proj, wqkv, wo, wf, wp);
    bias3_kernel<<<C_/256, 256>>>(bq, bk, bv, bqkv);
    ln_kernel<<<M_, 256>>>(x, ln1_g, ln1_b, ln);
    gemm_tc<<<gQKV, GTHREADS, GEMM_SMEM>>>(ln, wqkv, bqkv, nullptr,
                                           nullptr, qkv, C3_, C_, 3);
    attn_tc<<<dim3(T_ / 128, H_, B_), 256, ATTN_SMEM>>>(
        qkv, qkv + C_, qkv + 2 * C_, att, C3_);
    // launch 5: Wo projection (ncu -s 5 -c 1 captures THIS)
    gemm_tc<<<gC, GTHREADS, GEMM_SMEM>>>(att, wo, bo, x, x1, nullptr, C_, C_, 2);
    ln_kernel<<<M_, 256>>>(x1, ln2_g, ln2_b, ln);
    gemm_tc<<<gF, GTHREADS, GEMM_SMEM>>>(ln, wf, b_fc, nullptr,
                                         nullptr, fc, FC_, C_, 1);
    gemm_tc<<<gC, GTHREADS, GEMM_SMEM>>>(fc, wp, b_proj, x1, out,
                                         nullptr, C_, FC_, 2);
}

// round 15
// speedup vs baseline: 1.2656x; 1.0170x over previous
#include <cuda_runtime.h>
#include <cuda_fp16.h>
#include <math.h>
#include <stdint.h>

// ---------------------------------------------------------------------------
// GPT block: B=4, T=2048, C=1024, H=16, D=64
// ---------------------------------------------------------------------------
#define B_  4
#define T_  2048
#define C_  1024
#define C3_ (3 * C_)
#define H_  16
#define D_  64
#define M_  (B_ * T_)      // 8192
#define FC_ (4 * C_)       // 4096

// ---------------------------------------------------------------------------
// Helpers
// ---------------------------------------------------------------------------
__device__ __forceinline__ uint32_t smem_u32(const void* p) {
    uint32_t a;
    asm("{ .reg .u64 t; cvta.to.shared.u64 t, %1; cvt.u32.u64 %0, t; }"
        : "=r"(a) : "l"(p));
    return a;
}

__device__ __forceinline__ uint32_t pack_hi2(float a, float b) {
    __half2 t = __floats2half2_rn(a, b);
    return *(uint32_t*)&t;
}

__device__ __forceinline__ float gelu_f(float x)
{
    float x3 = x * x * x;
    return 0.5f * x * (1.0f + tanhf(0.7978845608028654f * (x + 0.044715f * x3)));
}

__device__ __forceinline__ void cpa16(uint32_t s, const void* g) {
    asm volatile("cp.async.ca.shared.global [%0], [%1], 16;" :: "r"(s), "l"(g));
}
#define CPA_COMMIT() asm volatile("cp.async.commit_group;" ::: "memory")
#define CPA_WAIT1()  asm volatile("cp.async.wait_group 1;" ::: "memory")
#define CPA_WAIT0()  asm volatile("cp.async.wait_group 0;" ::: "memory")

__device__ __forceinline__ void ldm4(uint32_t* r, uint32_t addr) {
    asm volatile("ldmatrix.sync.aligned.m8n8.x4.shared.b16 {%0,%1,%2,%3}, [%4];"
        : "=r"(r[0]), "=r"(r[1]), "=r"(r[2]), "=r"(r[3]) : "r"(addr));
}

// mma m16n8k16 row.col f32.f16.f16.f32
__device__ __forceinline__ void mma16816(float* d, const uint32_t* a, const uint32_t* b) {
    asm volatile("mma.sync.aligned.m16n8k16.row.col.f32.f16.f16.f32 "
        "{%0,%1,%2,%3}, {%4,%5,%6,%7}, {%8,%9}, {%0,%1,%2,%3};"
        : "+f"(d[0]), "+f"(d[1]), "+f"(d[2]), "+f"(d[3])
        : "r"(a[0]), "r"(a[1]), "r"(a[2]), "r"(a[3]), "r"(b[0]), "r"(b[1]));
}

// ---------------------------------------------------------------------------
// Scratch (static __device__) — fp16 activations/weights
// ---------------------------------------------------------------------------
__device__ __align__(128) __half g_ln  [M_ * C_];
__device__ __align__(128) __half g_att [M_ * C_];
__device__ __align__(128) __half g_fc  [M_ * FC_];
__device__ __align__(128) __half g_qkv [M_ * C3_];
__device__ __align__(128) __half g_wqkv[C3_ * C_];
__device__ __align__(128) __half g_wo  [C_ * C_];
__device__ __align__(128) __half g_wf  [FC_ * C_];
__device__ __align__(128) __half g_wp  [C_ * FC_];
__device__ __align__(128) float g_bqkv[C3_];
__device__ __align__(128) float g_x1[M_ * C_];

// ---------------------------------------------------------------------------
// ALL weight transposes + fp16 casts in ONE launch.
// ---------------------------------------------------------------------------
__global__ void wsplit_all(const float* __restrict__ Wq, const float* __restrict__ Wk,
                           const float* __restrict__ Wv, const float* __restrict__ Wo,
                           const float* __restrict__ Wfc, const float* __restrict__ Wpj,
                           __half* __restrict__ qkv, __half* __restrict__ wo,
                           __half* __restrict__ wf,  __half* __restrict__ wp)
{
    const int bid = blockIdx.x;
    const float* W;
    __half* Th;
    int K, N, t;
    if (bid < 3072) {
        int e = bid >> 10;  t = bid & 1023;
        W  = (e == 0) ? Wq : (e == 1) ? Wk : Wv;
        Th = qkv + (size_t)e * C_ * C_;
        K = C_;  N = C_;
    } else if (bid < 4096) {
        t = bid - 3072;  W = Wo;  Th = wo;  K = C_;  N = C_;
    } else if (bid < 8192) {
        t = bid - 4096;  W = Wfc; Th = wf;  K = C_;  N = FC_;
    } else {
        t = bid - 8192;  W = Wpj; Th = wp;  K = FC_; N = C_;
    }
    const int nX = N >> 5;
    const int bx = t % nX, by = t / nX;

    __shared__ float ts[32][33];
    int tx = threadIdx.x & 31, ty = threadIdx.x >> 5;
    #pragma unroll
    for (int i = 0; i < 4; i++) {
        int k = by * 32 + ty + i * 8;
        ts[ty + i * 8][tx] = W[(size_t)k * N + bx * 32 + tx];
    }
    __syncthreads();
    #pragma unroll
    for (int i = 0; i < 4; i++) {
        int n = bx * 32 + ty + i * 8;
        int k = by * 32 + tx;
        Th[(size_t)n * K + k] = __float2half(ts[tx][ty + i * 8]);
    }
}

__global__ void bias3_kernel(const float* __restrict__ a, const float* __restrict__ b,
                             const float* __restrict__ c, float* __restrict__ o)
{
    int i = blockIdx.x * 256 + threadIdx.x;
    if (i < C_) { o[i] = a[i]; o[C_ + i] = b[i]; o[2 * C_ + i] = c[i]; }
}

// ---------------------------------------------------------------------------
// LayerNorm -> fp16
// ---------------------------------------------------------------------------
__global__ void ln_kernel(const float* __restrict__ x,
                          const float* __restrict__ gamma,
                          const float* __restrict__ beta,
                          __half* __restrict__ y)
{
    int row = blockIdx.x;
    int t   = threadIdx.x;
    const float4* xr = (const float4*)(x + (size_t)row * C_);
    float4 xv = xr[t];

    float s  = xv.x + xv.y + xv.z + xv.w;
    float ss = fmaf(xv.x, xv.x, fmaf(xv.y, xv.y, fmaf(xv.z, xv.z, xv.w * xv.w)));
    #pragma unroll
    for (int o = 16; o > 0; o >>= 1) {
        s  += __shfl_xor_sync(0xffffffffu, s,  o);
        ss += __shfl_xor_sync(0xffffffffu, ss, o);
    }
    __shared__ float rs[8], rss[8];
    __shared__ float s_mu, s_inv;
    int w = t >> 5, lane = t & 31;
    if (lane == 0) { rs[w] = s; rss[w] = ss; }
    __syncthreads();
    if (t == 0) {
        float ts = 0.f, tss = 0.f;
        #pragma unroll
        for (int i = 0; i < 8; i++) { ts += rs[i]; tss += rss[i]; }
        float mu  = ts * (1.0f / (float)C_);
        float var = tss * (1.0f / (float)C_) - mu * mu;
        s_mu = mu;  s_inv = rsqrtf(var + 1e-5f);
    }
    __syncthreads();
    float mu = s_mu, inv = s_inv;

    float4 gv = ((const float4*)gamma)[t];
    float4 bv = ((const float4*)beta)[t];
    float o0 = (xv.x - mu) * inv * gv.x + bv.x;
    float o1 = (xv.y - mu) * inv * gv.y + bv.y;
    float o2 = (xv.z - mu) * inv * gv.z + bv.z;
    float o3 = (xv.w - mu) * inv * gv.w + bv.w;

    uint2 u;
    u.x = pack_hi2(o0, o1);
    u.y = pack_hi2(o2, o3);
    ((uint2*)(y + (size_t)row * C_))[t] = u;
}

// ---------------------------------------------------------------------------
// Tensor-core GEMM via mma.sync (pure fp16, fp32 accum)
// CTA tile 128x256, BK=64, 256 threads (8 warps, 2M x 4N, warp 64x64).
// Warp tile 64x64: 8 ldm4 per 32 MMAs (0.25 ratio vs 0.375 prior) —
// halves the LDSM smem traffic per FLOP (crossbar was the binding limit).
// 3-stage cp.async pipeline, one sync per BK=64 chunk.
// ---------------------------------------------------------------------------
#define ROWB_ 144                         // 128B data + 16B pad
#define A_TILE_B (128 * ROWB_)            // 18432
#define B_TILE_B (256 * ROWB_)            // 36864
#define STAGE_B  (A_TILE_B + B_TILE_B)    // 55296
#define NSTAGE   3
#define GEMM_SMEM (NSTAGE * STAGE_B)      // 165888
#define oA_ 0
#define oB_ A_TILE_B
#define GTHREADS 256

__device__ __forceinline__ void gemm_load_stage(
    uint32_t sbb, const char* gA, const char* gB,
    size_t rowBytes, size_t kb, int tid)
{
    // A: 128 rows x 8 segs of 16B = 1024 segs
    #pragma unroll
    for (int i = 0; i < 4; i++) {
        int s = tid + i * 256;
        int r = s >> 3, c = (s & 7) * 16;
        cpa16(sbb + oA_ + r * ROWB_ + c, gA + (size_t)r * rowBytes + kb + c);
    }
    // B: 256 rows x 8 segs = 2048 segs
    #pragma unroll
    for (int i = 0; i < 8; i++) {
        int s = tid + i * 256;
        int r = s >> 3, c = (s & 7) * 16;
        cpa16(sbb + oB_ + r * ROWB_ + c, gB + (size_t)r * rowBytes + kb + c);
    }
    CPA_COMMIT();
}

__global__ void __launch_bounds__(GTHREADS, 1)
gemm_tc(const __half* __restrict__ A,
        const __half* __restrict__ Bm,
        const float* __restrict__ bias, const float* __restrict__ resid,
        float* __restrict__ Cout, __half* __restrict__ outH,
        int Nn, int Kk, int epi)
{
    extern __shared__ __align__(128) char smem[];
    const uint32_t sb = smem_u32(smem);

    const int tid  = threadIdx.x;
    const int wid  = tid >> 5;
    const int lane = tid & 31;
    const int bx = blockIdx.x;      // N tile (256)
    const int by = blockIdx.y;      // M tile (128)
    const int wm = wid >> 2;        // 0..1  rows wm*64..+63
    const int wn = wid & 3;         // 0..3  cols wn*64..+63

    const char* gA = (const char*)(A  + (size_t)(by * 128) * Kk);
    const char* gB = (const char*)(Bm + (size_t)(bx * 256) * Kk);
    const size_t rowBytes = (size_t)Kk * 2;

    const uint32_t aRowOff = (uint32_t)((wm * 64 + (lane & 15)) * ROWB_ + (lane >> 4) * 16);
    const uint32_t bRowOff = (uint32_t)((wn * 64 + (lane & 7) + ((lane >> 4) << 3)) * ROWB_
                                        + ((lane >> 3) & 1) * 16);

    float acc[4][8][4];
    #pragma unroll
    for (int mt = 0; mt < 4; mt++)
        #pragma unroll
        for (int nt = 0; nt < 8; nt++)
            #pragma unroll
            for (int e = 0; e < 4; e++) acc[mt][nt][e] = 0.f;

    const int nch = Kk >> 6;   // BK=64

    gemm_load_stage(sb,           gA, gB, rowBytes, 0,   tid);
    gemm_load_stage(sb + STAGE_B, gA, gB, rowBytes, 128, tid);

    for (int ch = 0; ch < nch; ch++) {
        if (ch == nch - 1) { CPA_WAIT0(); } else { CPA_WAIT1(); }
        __syncthreads();
        if (ch + 2 < nch) {
            gemm_load_stage(sb + ((ch + 2) % NSTAGE) * STAGE_B,
                            gA, gB, rowBytes, (size_t)(ch + 2) * 128, tid);
        }

        const uint32_t buf = sb + (ch % NSTAGE) * STAGE_B;
        const uint32_t aP = buf + oA_ + aRowOff;
        const uint32_t bP = buf + oB_ + bRowOff;

        #pragma unroll
        for (int ks = 0; ks < 4; ks++) {
            const uint32_t ko = (uint32_t)(ks * 32);
            uint32_t af[4][4];
            #pragma unroll
            for (int mt = 0; mt < 4; mt++)
                ldm4(af[mt], aP + (uint32_t)(mt * 16 * ROWB_) + ko);
            #pragma unroll
            for (int p = 0; p < 4; p++) {
                uint32_t rh[4];
                ldm4(rh, bP + (uint32_t)(p * 16 * ROWB_) + ko);
                const int nt0 = 2 * p, nt1 = 2 * p + 1;
                #pragma unroll
                for (int mt = 0; mt < 4; mt++) {
                    mma16816(acc[mt][nt0], af[mt], rh);
                    mma16816(acc[mt][nt1], af[mt], rh + 2);
                }
            }
        }
    }

    // epilogue
    const int rowBase = by * 128 + wm * 64 + (lane >> 2);
    const int colBase = bx * 256 + wn * 64 + (lane & 3) * 2;
    #pragma unroll
    for (int mt = 0; mt < 4; mt++) {
        #pragma unroll
        for (int nt = 0; nt < 8; nt++) {
            const int col = colBase + nt * 8;
            const float b0 = bias[col], b1 = bias[col + 1];
            const int ra = rowBase + mt * 16;
            const int rb = ra + 8;
            float v00 = acc[mt][nt][0] + b0, v01 = acc[mt][nt][1] + b1;
            float v10 = acc[mt][nt][2] + b0, v11 = acc[mt][nt][3] + b1;
            if (epi == 1 || epi == 3) {
                if (epi == 1) {
                    v00 = gelu_f(v00); v01 = gelu_f(v01);
                    v10 = gelu_f(v10); v11 = gelu_f(v11);
                }
                *(uint32_t*)&outH[(size_t)ra * Nn + col] = pack_hi2(v00, v01);
                *(uint32_t*)&outH[(size_t)rb * Nn + col] = pack_hi2(v10, v11);
            } else {
                if (epi == 2) {
                    const float2 r0v = *(const float2*)&resid[(size_t)ra * Nn + col];
                    const float2 r1v = *(const float2*)&resid[(size_t)rb * Nn + col];
                    v00 += r0v.x; v01 += r0v.y; v10 += r1v.x; v11 += r1v.y;
                }
                *(float2*)&Cout[(size_t)ra * Nn + col] = make_float2(v00, v01);
                *(float2*)&Cout[(size_t)rb * Nn + col] = make_float2(v10, v11);
            }
        }
    }
}

// ---------------------------------------------------------------------------
// Tensor-core flash attention (pure fp16, causal). 2 CTAs/SM.
// qt reversed: heavy tiles first.
// ---------------------------------------------------------------------------
#define STR_ 72
#define SQ_BYTES (128 * STR_ * 2)
#define SK_BYTES (64 * STR_ * 2)
#define ATTN_SMEM (SQ_BYTES + 2 * SK_BYTES)   // 36864

__global__ void __launch_bounds__(256, 2)
attn_tc(const __half* __restrict__ Q_, const __half* __restrict__ K_,
        const __half* __restrict__ V_,
        __half* __restrict__ O_, int qkvStride)
{
    extern __shared__ __align__(128) char smem[];
    const uint32_t sQ = smem_u32(smem);
    const uint32_t sK = sQ + SQ_BYTES;
    const uint32_t sV = sK + SK_BYTES;
    __half* mV = (__half*)(smem + SQ_BYTES + SK_BYTES);

    const int qt = (int)gridDim.x - 1 - (int)blockIdx.x;   // heavy first
    const int h = blockIdx.y, b = blockIdx.z;
    const int tid = threadIdx.x, wid = tid >> 5, lane = tid & 31;
    const int wm = wid;

    const size_t rowB = (size_t)qkvStride * 2;
    const size_t qbase = ((size_t)(b * T_ + qt * 128)) * rowB + (size_t)h * 128;

    #pragma unroll
    for (int i = 0; i < 4; i++) {
        int c = tid + i * 256;
        int r = c >> 3, ch = (c & 7) * 16;
        cpa16(sQ + r * 144 + ch, (const char*)Q_ + qbase + (size_t)r * rowB + ch);
    }
    CPA_COMMIT();

    const uint32_t aOff  = (uint32_t)((wm * 16 + (lane & 15)) * 144 + (lane >> 4) * 16);
    const uint32_t bRow  = (uint32_t)((lane & 7) + ((lane >> 4) << 3));
    const uint32_t bByte = (uint32_t)(((lane >> 3) & 1) * 16);

    uint32_t qf[4][4];
    float oacc[8][4];
    #pragma unroll
    for (int nd = 0; nd < 8; nd++)
        #pragma unroll
        for (int e = 0; e < 4; e++) oacc[nd][e] = 0.f;
    float m0 = -1e30f, m1 = -1e30f, l0 = 0.f, l1 = 0.f;

    const int qr0 = qt * 128 + wm * 16 + (lane >> 2);
    const int nkt = 2 * qt + 2;

    for (int kt = 0; kt < nkt; kt++) {
        __syncthreads();
        const size_t kbase = ((size_t)(b * T_ + kt * 64)) * rowB + (size_t)h * 128;
        #pragma unroll
        for (int i = 0; i < 2; i++) {
            int c = tid + i * 256;
            int r = c >> 3, ch = (c & 7) * 16;
            cpa16(sK + r * 144 + ch, (const char*)K_ + kbase + (size_t)r * rowB + ch);
        }
        CPA_COMMIT();

        uint4 vreg[2];
        int vkey[2], vd0[2];
        #pragma unroll
        for (int i = 0; i < 2; i++) {
            int c = tid + i * 256;
            vkey[i] = c & 63;
            vd0[i]  = (c >> 6) * 8;
            vreg[i] = *(const uint4*)((const char*)V_ + kbase + (size_t)vkey[i] * rowB + (c >> 6) * 16);
        }

        CPA_WAIT0();

        #pragma unroll
        for (int i = 0; i < 2; i++) {
            const __half* eh = (const __half*)&vreg[i];
            #pragma unroll
            for (int j = 0; j < 8; j++)
                mV[(vd0[i] + j) * STR_ + vkey[i]] = eh[j];
        }
        __syncthreads();

        if (kt == 0) {
            #pragma unroll
            for (int ks = 0; ks < 4; ks++)
                ldm4(qf[ks], sQ + aOff + ks * 32);
        }

        // S = Q.K^T
        float sa[8][4];
        #pragma unroll
        for (int nt = 0; nt < 8; nt++)
            #pragma unroll
            for (int e = 0; e < 4; e++) sa[nt][e] = 0.f;

        #pragma unroll
        for (int ks = 0; ks < 4; ks++) {
            uint32_t bh[8][2];
            #pragma unroll
            for (int p = 0; p < 4; p++) {
                uint32_t rh[4];
                ldm4(rh, sK + (p * 16 + bRow) * 144 + bByte + ks * 32);
                bh[2 * p][0] = rh[0]; bh[2 * p][1] = rh[1];
                bh[2 * p + 1][0] = rh[2]; bh[2 * p + 1][1] = rh[3];
            }
            #pragma unroll
            for (int nt = 0; nt < 8; nt++) mma16816(sa[nt], qf[ks], bh[nt]);
        }

        // online softmax
        float tm0 = -1e30f, tm1 = -1e30f;
        #pragma unroll
        for (int nt = 0; nt < 8; nt++) {
            #pragma unroll
            for (int j = 0; j < 2; j++) {
                int kcol = kt * 64 + nt * 8 + (lane & 3) * 2 + j;
                float s0 = sa[nt][j] * 0.125f;
                float s1 = sa[nt][2 + j] * 0.125f;
                if (kcol > qr0)     s0 = -1e30f;
                if (kcol > qr0 + 8) s1 = -1e30f;
                sa[nt][j] = s0;  sa[nt][2 + j] = s1;
                tm0 = fmaxf(tm0, s0);  tm1 = fmaxf(tm1, s1);
            }
        }
        tm0 = fmaxf(tm0, __shfl_xor_sync(0xffffffffu, tm0, 1));
        tm0 = fmaxf(tm0, __shfl_xor_sync(0xffffffffu, tm0, 2));
        tm1 = fmaxf(tm1, __shfl_xor_sync(0xffffffffu, tm1, 1));
        tm1 = fmaxf(tm1, __shfl_xor_sync(0xffffffffu, tm1, 2));

        const float nm0 = fmaxf(m0, tm0), nm1 = fmaxf(m1, tm1);
        const float cr0 = __expf(m0 - nm0), cr1 = __expf(m1 - nm1);
        m0 = nm0; m1 = nm1;

        float rs0 = 0.f, rs1 = 0.f;
        #pragma unroll
        for (int nt = 0; nt < 8; nt++) {
            #pragma unroll
            for (int j = 0; j < 2; j++) {
                float p0 = __expf(sa[nt][j] - m0);
                float p1 = __expf(sa[nt][2 + j] - m1);
                sa[nt][j] = p0;  sa[nt][2 + j] = p1;
                rs0 += p0;  rs1 += p1;
            }
        }
        rs0 += __shfl_xor_sync(0xffffffffu, rs0, 1);
        rs0 += __shfl_xor_sync(0xffffffffu, rs0, 2);
        rs1 += __shfl_xor_sync(0xffffffffu, rs1, 1);
        rs1 += __shfl_xor_sync(0xffffffffu, rs1, 2);
        l0 = l0 * cr0 + rs0;
        l1 = l1 * cr1 + rs1;

        #pragma unroll
        for (int nd = 0; nd < 8; nd++) {
            oacc[nd][0] *= cr0; oacc[nd][1] *= cr0;
            oacc[nd][2] *= cr1; oacc[nd][3] *= cr1;
        }

        uint32_t pH[4][4];
        #pragma unroll
        for (int ks = 0; ks < 4; ks++) {
            const int t0 = 2 * ks, t1 = 2 * ks + 1;
            pH[ks][0] = pack_hi2(sa[t0][0], sa[t0][1]);
            pH[ks][1] = pack_hi2(sa[t0][2], sa[t0][3]);
            pH[ks][2] = pack_hi2(sa[t1][0], sa[t1][1]);
            pH[ks][3] = pack_hi2(sa[t1][2], sa[t1][3]);
        }

        // O += P.V
        #pragma unroll
        for (int ks = 0; ks < 4; ks++) {
            uint32_t vh[8][2];
            #pragma unroll
            for (int p = 0; p < 4; p++) {
                uint32_t rh[4];
                ldm4(rh, sV + (p * 16 + bRow) * 144 + bByte + ks * 32);
                vh[2 * p][0] = rh[0]; vh[2 * p][1] = rh[1];
                vh[2 * p + 1][0] = rh[2]; vh[2 * p + 1][1] = rh[3];
            }
            #pragma unroll
            for (int nd = 0; nd < 8; nd++) mma16816(oacc[nd], pH[ks], vh[nd]);
        }
    }

    const float il0 = 1.0f / l0, il1 = 1.0f / l1;
    const size_t tok0 = (size_t)(b * T_ + qt * 128 + wm * 16 + (lane >> 2));
    const int colb = h * 64 + (lane & 3) * 2;
    #pragma unroll
    for (int nd = 0; nd < 8; nd++) {
        const int col = colb + nd * 8;
        *(uint32_t*)&O_[tok0 * C_ + col]       = pack_hi2(oacc[nd][0] * il0, oacc[nd][1] * il0);
        *(uint32_t*)&O_[(tok0 + 8) * C_ + col] = pack_hi2(oacc[nd][2] * il1, oacc[nd][3] * il1);
    }
}

// ---------------------------------------------------------------------------
// Launch
// ---------------------------------------------------------------------------
extern "C" void kernel_launch(void* const* d_in, const int* in_sizes, int n_in,
                              void* d_out, int out_size)
{
    const float* x      = (const float*)d_in[0];
    const float* Wq     = (const float*)d_in[1];
    const float* bq     = (const float*)d_in[2];
    const float* Wk     = (const float*)d_in[3];
    const float* bk     = (const float*)d_in[4];
    const float* Wv     = (const float*)d_in[5];
    const float* bv     = (const float*)d_in[6];
    const float* Wo     = (const float*)d_in[7];
    const float* bo     = (const float*)d_in[8];
    const float* ln1_g  = (const float*)d_in[9];
    const float* ln1_b  = (const float*)d_in[10];
    const float* ln2_g  = (const float*)d_in[11];
    const float* ln2_b  = (const float*)d_in[12];
    const float* W_fc   = (const float*)d_in[13];
    const float* b_fc   = (const float*)d_in[14];
    const float* W_proj = (const float*)d_in[15];
    const float* b_proj = (const float*)d_in[16];
    float* out = (float*)d_out;

    __half *ln, *att, *fc, *qkv, *wqkv, *wo, *wf, *wp;
    float *x1, *bqkv;
    cudaGetSymbolAddress((void**)&ln,   g_ln);
    cudaGetSymbolAddress((void**)&att,  g_att);
    cudaGetSymbolAddress((void**)&fc,   g_fc);
    cudaGetSymbolAddress((void**)&qkv,  g_qkv);
    cudaGetSymbolAddress((void**)&wqkv, g_wqkv);
    cudaGetSymbolAddress((void**)&wo,   g_wo);
    cudaGetSymbolAddress((void**)&wf,   g_wf);
    cudaGetSymbolAddress((void**)&wp,   g_wp);
    cudaGetSymbolAddress((void**)&x1,   g_x1);
    cudaGetSymbolAddress((void**)&bqkv, g_bqkv);

    cudaFuncSetAttribute(attn_tc, cudaFuncAttributeMaxDynamicSharedMemorySize, ATTN_SMEM);
    cudaFuncSetAttribute(gemm_tc, cudaFuncAttributeMaxDynamicSharedMemorySize, GEMM_SMEM);

    dim3 gQKV(C3_ / 256, M_ / 128);   // (12, 64)
    dim3 gC  (C_  / 256, M_ / 128);   // (4, 64)
    dim3 gF  (FC_ / 256, M_ / 128);   // (16, 64)

    wsplit_all<<<12288, 256>>>(Wq, Wk, Wv, Wo, W_fc, W_proj, wqkv, wo, wf, wp);
    bias3_kernel<<<C_/256, 256>>>(bq, bk, bv, bqkv);
    ln_kernel<<<M_, 256>>>(x, ln1_g, ln1_b, ln);
    gemm_tc<<<gQKV, GTHREADS, GEMM_SMEM>>>(ln, wqkv, bqkv, nullptr,
                                           nullptr, qkv, C3_, C_, 3);
    attn_tc<<<dim3(T_ / 128, H_, B_), 256, ATTN_SMEM>>>(
        qkv, qkv + C_, qkv + 2 * C_, att, C3_);
    // launch 5: Wo projection (ncu -s 5 -c 1 captures THIS)
    gemm_tc<<<gC, GTHREADS, GEMM_SMEM>>>(att, wo, bo, x, x1, nullptr, C_, C_, 2);
    ln_kernel<<<M_, 256>>>(x1, ln2_g, ln2_b, ln);
    gemm_tc<<<gF, GTHREADS, GEMM_SMEM>>>(ln, wf, b_fc, nullptr,
                                         nullptr, fc, FC_, C_, 1);
    gemm_tc<<<gC, GTHREADS, GEMM_SMEM>>>(fc, wp, b_proj, x1, out,
                                         nullptr, C_, FC_, 2);
}